// round 16
// baseline (speedup 1.0000x reference)
#include <cuda_runtime.h>
#include <cuda_bf16.h>
#include <cuda_fp16.h>
#include <cstdint>

#define B_DIM 4096
#define N_CIT 16
#define D_IN  1024
#define D_OUT 1024
#define KTOT  (N_CIT * D_IN)
#define EPSV  0.01f
#define LSPLIT 4

__device__ float g_lpart[LSPLIT * B_DIM * 256];
__device__ float g_power [B_DIM * 16];
__device__ __half g_wf16[(size_t)D_OUT * KTOT];   // [o][k] K-major, fp16
__device__ __half g_byf16[(size_t)D_OUT * 64];    // [o][k] k 0..15 real, 16..63 zero
__device__ __nv_bfloat16 g_wd_hi[256 * D_IN];
__device__ __nv_bfloat16 g_wd_lo[256 * D_IN];

__device__ __forceinline__ uint32_t smem_to_u32(const void* p) {
    uint32_t a;
    asm("{ .reg .u64 t; cvta.to.shared.u64 t, %1; cvt.u32.u64 %0, t; }" : "=r"(a) : "l"(p));
    return a;
}
// 64B-row swizzle (logits path)
__device__ __forceinline__ uint32_t sw(uint32_t base, int row, int q) {
    return base + row * 64 + (((uint32_t)(q ^ ((row >> 1) & 3))) << 4);
}
// 128B-row swizzle (main path)
__device__ __forceinline__ uint32_t sw128(uint32_t base, int row, int q) {
    return base + row * 128 + (((uint32_t)(q ^ (row & 7))) << 4);
}
__device__ __forceinline__ uint32_t pack_bf16(float f0, float f1) {
    uint32_t r;
    asm("cvt.rn.bf16x2.f32 %0, %1, %2;" : "=r"(r) : "f"(f1), "f"(f0));
    return r;
}
__device__ __forceinline__ uint32_t pack_f16f(float f0, float f1) {
    uint32_t r;
    asm("cvt.rn.f16x2.f32 %0, %1, %2;" : "=r"(r) : "f"(f1), "f"(f0));
    return r;
}
#define CP_ASYNC16(dst, src) \
    asm volatile("cp.async.cg.shared.global [%0], [%1], 16;" :: "r"(dst), "l"(src) : "memory")
#define CP_COMMIT() asm volatile("cp.async.commit_group;" ::: "memory")
#define CP_WAIT0()  asm volatile("cp.async.wait_group 0;" ::: "memory")
#define LDSM4(r, addr) \
    asm volatile("ldmatrix.sync.aligned.m8n8.x4.shared.b16 {%0,%1,%2,%3}, [%4];" \
        : "=r"((r)[0]), "=r"((r)[1]), "=r"((r)[2]), "=r"((r)[3]) : "r"(addr))
#define MMA_BF16(d, a, b) \
    asm volatile("mma.sync.aligned.m16n8k16.row.col.f32.bf16.bf16.f32 " \
        "{%0,%1,%2,%3}, {%4,%5,%6,%7}, {%8,%9}, {%0,%1,%2,%3};" \
        : "+f"((d)[0]), "+f"((d)[1]), "+f"((d)[2]), "+f"((d)[3]) \
        : "r"((a)[0]), "r"((a)[1]), "r"((a)[2]), "r"((a)[3]), "r"((b)[0]), "r"((b)[1]))
#define MMA_F16(d, a, b) \
    asm volatile("mma.sync.aligned.m16n8k16.row.col.f32.f16.f16.f32 " \
        "{%0,%1,%2,%3}, {%4,%5,%6,%7}, {%8,%9}, {%0,%1,%2,%3};" \
        : "+f"((d)[0]), "+f"((d)[1]), "+f"((d)[2]), "+f"((d)[3]) \
        : "r"((a)[0]), "r"((a)[1]), "r"((a)[2]), "r"((a)[3]), "r"((b)[0]), "r"((b)[1]))
#define STS128(addr, r0, r1, r2, r3) \
    asm volatile("st.shared.v4.b32 [%0], {%1,%2,%3,%4};" \
        :: "r"(addr), "r"(r0), "r"(r1), "r"(r2), "r"(r3) : "memory")

// ============================================================================
// Kernel 0a: transpose + fp16 round: Wy[16384,1024] -> g_wf16[1024][16384]
// ============================================================================
__global__ __launch_bounds__(256) void transpose_f16(const float* __restrict__ Wy)
{
    __shared__ float T[64][65];
    const int k0 = blockIdx.x * 64;
    const int o0 = blockIdx.y * 64;
    const int tid = threadIdx.x;
    {
        int kr = tid >> 4, o4 = tid & 15;
        #pragma unroll
        for (int r = 0; r < 4; r++) {
            int k = kr + r * 16;
            float4 v = *(const float4*)&Wy[(size_t)(k0 + k) * D_OUT + o0 + o4 * 4];
            T[k][o4 * 4 + 0] = v.x;  T[k][o4 * 4 + 1] = v.y;
            T[k][o4 * 4 + 2] = v.z;  T[k][o4 * 4 + 3] = v.w;
        }
    }
    __syncthreads();
    {
        int o = tid >> 2, kq = tid & 3;
        uint32_t hv[8];
        #pragma unroll
        for (int i = 0; i < 8; i++)
            hv[i] = pack_f16f(T[kq * 16 + i * 2][o], T[kq * 16 + i * 2 + 1][o]);
        size_t dst = (size_t)(o0 + o) * KTOT + k0 + kq * 16;
        *(uint4*)&g_wf16[dst]     = make_uint4(hv[0], hv[1], hv[2], hv[3]);
        *(uint4*)&g_wf16[dst + 8] = make_uint4(hv[4], hv[5], hv[6], hv[7]);
    }
}

// ============================================================================
// Kernel 0b: by -> g_byf16[1024][64] fp16 (k 16..63 zero)
// ============================================================================
__global__ __launch_bounds__(256) void by_prep(const float* __restrict__ by)
{
    int o = blockIdx.x * 256 + threadIdx.x;
    if (o >= D_OUT) return;
    #pragma unroll
    for (int kp = 0; kp < 8; kp++) {
        *(uint32_t*)&g_byf16[(size_t)o * 64 + kp * 2] =
            pack_f16f(by[(size_t)(kp * 2) * D_OUT + o],
                      by[(size_t)(kp * 2 + 1) * D_OUT + o]);
    }
    #pragma unroll
    for (int kp = 8; kp < 32; kp++)
        *(uint32_t*)&g_byf16[(size_t)o * 64 + kp * 2] = 0u;
}

// ============================================================================
// Kernel 0c: Wd -> g_wd (K-major, bf16 hi/lo) — logits path
// ============================================================================
__global__ __launch_bounds__(256) void wd_prep(const float* __restrict__ Wd)
{
    const int c = blockIdx.x;
    const int n = c >> 4, j = c & 15;
    const int tid = threadIdx.x;
    const float* src = Wd + (size_t)n * (D_IN * 16) + j;
    int k = tid * 4;
    float a0 = src[(size_t)(k + 0) * 16];
    float a1 = src[(size_t)(k + 1) * 16];
    float a2 = src[(size_t)(k + 2) * 16];
    float a3 = src[(size_t)(k + 3) * 16];
    uint32_t h0 = pack_bf16(a0, a1);
    uint32_t h1 = pack_bf16(a2, a3);
    float f0 = __uint_as_float(h0 << 16);
    float f1 = __uint_as_float(h0 & 0xFFFF0000u);
    float f2 = __uint_as_float(h1 << 16);
    float f3 = __uint_as_float(h1 & 0xFFFF0000u);
    *(uint2*)&g_wd_hi[(size_t)c * D_IN + k] = make_uint2(h0, h1);
    *(uint2*)&g_wd_lo[(size_t)c * D_IN + k] =
        make_uint2(pack_bf16(a0 - f0, a1 - f1), pack_bf16(a2 - f2, a3 - f3));
}

// ============================================================================
// logits path (split-bf16, unchanged from best)
// ============================================================================
__device__ __forceinline__ void math_kh(uint32_t cb, int kh, int wm, int wn,
                                        int j, int rr, float acc[4][8][4])
{
    uint32_t afh[4][4], afl[4][4];
    #pragma unroll
    for (int t = 0; t < 4; t++) {
        int row = wm + t * 16 + ((j & 1) << 3) + rr;
        int q = kh * 2 + (j >> 1);
        LDSM4(afh[t], sw(cb, row, q));
        LDSM4(afl[t], sw(cb + 8192, row, q));
    }
    #pragma unroll
    for (int uh = 0; uh < 2; uh++) {
        uint32_t bfh[4][2], bfl[4][2];
        #pragma unroll
        for (int up = 0; up < 2; up++) {
            int u0 = uh * 4 + up * 2;
            int nrow = wn + u0 * 8 + ((j >> 1) << 3) + rr;
            int q = kh * 2 + (j & 1);
            uint32_t t4[4];
            LDSM4(t4, sw(cb + 16384, nrow, q));
            bfh[up * 2][0] = t4[0]; bfh[up * 2][1] = t4[1];
            bfh[up * 2 + 1][0] = t4[2]; bfh[up * 2 + 1][1] = t4[3];
            LDSM4(t4, sw(cb + 32768, nrow, q));
            bfl[up * 2][0] = t4[0]; bfl[up * 2][1] = t4[1];
            bfl[up * 2 + 1][0] = t4[2]; bfl[up * 2 + 1][1] = t4[3];
        }
        #pragma unroll
        for (int t = 0; t < 4; t++)
            #pragma unroll
            for (int uu = 0; uu < 4; uu++)
                MMA_BF16(acc[t][uh * 4 + uu], afh[t], bfh[uu]);
        #pragma unroll
        for (int t = 0; t < 4; t++)
            #pragma unroll
            for (int uu = 0; uu < 4; uu++)
                MMA_BF16(acc[t][uh * 4 + uu], afh[t], bfl[uu]);
        #pragma unroll
        for (int t = 0; t < 4; t++)
            #pragma unroll
            for (int uu = 0; uu < 4; uu++)
                MMA_BF16(acc[t][uh * 4 + uu], afl[t], bfh[uu]);
    }
}

#define LBUFSTRIDE 49152
#define LSMEM_TOTAL (2 * LBUFSTRIDE)
#define LSTG (D_IN / 32 / LSPLIT)

__device__ __forceinline__ void cp_b_logits(uint32_t buf, int kc, int tid)
{
    size_t off = ((size_t)tid * D_IN + (size_t)kc * 32) * 2;
    const char* sh = (const char*)g_wd_hi + off;
    const char* sl = (const char*)g_wd_lo + off;
    uint32_t bh = buf + 16384, bl = buf + 32768;
    #pragma unroll
    for (int q = 0; q < 4; q++) {
        CP_ASYNC16(sw(bh, tid, q), sh + q * 16);
        CP_ASYNC16(sw(bl, tid, q), sl + q * 16);
    }
}

__device__ __forceinline__ void gen_a_logits(uint32_t buf, const float* __restrict__ x,
                                             int bm, int kc, int tid)
{
    const int ar = tid >> 1;
    const int half = tid & 1;
    float v[16];
    const float* xp = x + (size_t)(bm + ar) * D_IN + kc * 32 + half * 16;
    #pragma unroll
    for (int q = 0; q < 4; q++) {
        float4 t4 = *(const float4*)(xp + q * 4);
        v[q * 4 + 0] = t4.x; v[q * 4 + 1] = t4.y;
        v[q * 4 + 2] = t4.z; v[q * 4 + 3] = t4.w;
    }
    #pragma unroll
    for (int q2 = 0; q2 < 2; q2++) {
        uint32_t hi4[4], lo4[4];
        #pragma unroll
        for (int i = 0; i < 4; i++) {
            float f0 = v[q2 * 8 + i * 2];
            float f1 = v[q2 * 8 + i * 2 + 1];
            uint32_t hb = pack_bf16(f0, f1);
            float fh0 = __uint_as_float(hb << 16);
            float fh1 = __uint_as_float(hb & 0xFFFF0000u);
            hi4[i] = hb;
            lo4[i] = pack_bf16(f0 - fh0, f1 - fh1);
        }
        int q = half * 2 + q2;
        STS128(sw(buf, ar, q),        hi4[0], hi4[1], hi4[2], hi4[3]);
        STS128(sw(buf + 8192, ar, q), lo4[0], lo4[1], lo4[2], lo4[3]);
    }
}

__global__ __launch_bounds__(256, 1) void logits_mma(const float* __restrict__ x)
{
    extern __shared__ char smem[];
    const uint32_t sb = smem_to_u32(smem);
    const int tid = threadIdx.x;
    const int lane = tid & 31, w = tid >> 5;
    const int ks = blockIdx.x;
    const int bm = blockIdx.y * 128;
    const int wm = (w & 1) * 64, wn = (w >> 1) * 64;
    const int kc0 = ks * LSTG;

    float acc[4][8][4];
    #pragma unroll
    for (int t = 0; t < 4; t++)
        #pragma unroll
        for (int u = 0; u < 8; u++)
            #pragma unroll
            for (int c = 0; c < 4; c++) acc[t][u][c] = 0.f;

    cp_b_logits(sb, kc0, tid);
    CP_COMMIT();
    gen_a_logits(sb, x, bm, kc0, tid);
    CP_WAIT0();
    __syncthreads();

    const int j = lane >> 3, rr = lane & 7;
    for (int s = 0; s < LSTG; s++) {
        const uint32_t cb = sb + (uint32_t)(s & 1) * LBUFSTRIDE;
        const uint32_t nb = sb + (uint32_t)((s + 1) & 1) * LBUFSTRIDE;
        const bool has_next = (s + 1 < LSTG);
        if (has_next) { cp_b_logits(nb, kc0 + s + 1, tid); CP_COMMIT(); }
        math_kh(cb, 0, wm, wn, j, rr, acc);
        if (has_next) gen_a_logits(nb, x, bm, kc0 + s + 1, tid);
        math_kh(cb, 1, wm, wn, j, rr, acc);
        if (has_next) CP_WAIT0();
        __syncthreads();
    }

    float* lp = g_lpart + (size_t)ks * (B_DIM * 256);
    #pragma unroll
    for (int t = 0; t < 4; t++) {
        int row0 = bm + wm + t * 16 + (lane >> 2);
        #pragma unroll
        for (int u = 0; u < 8; u++) {
            int col = wn + u * 8 + (lane & 3) * 2;
            *(float2*)&lp[(size_t)row0 * 256 + col] =
                make_float2(acc[t][u][0], acc[t][u][1]);
            *(float2*)&lp[(size_t)(row0 + 8) * 256 + col] =
                make_float2(acc[t][u][2], acc[t][u][3]);
        }
    }
}

// ============================================================================
// power: sum partials + bd, softmax + warp-parallel 16x16 solve
// ============================================================================
__global__ __launch_bounds__(256) void power_kernel(const float* __restrict__ bd)
{
    const int tid = threadIdx.x;
    const int lane = tid & 31;
    const int l16 = lane & 15;
    const int b = blockIdx.x * 16 + (tid >> 4);
    const float ome = 1.f - EPSV;

    float d[16];
    {
        size_t base = (size_t)b * 256 + l16 * 16;
        #pragma unroll
        for (int q = 0; q < 4; q++) {
            float4 t0 = *(const float4*)(g_lpart + base + q * 4);
            float4 t1 = *(const float4*)(g_lpart + (size_t)1 * B_DIM * 256 + base + q * 4);
            float4 t2 = *(const float4*)(g_lpart + (size_t)2 * B_DIM * 256 + base + q * 4);
            float4 t3 = *(const float4*)(g_lpart + (size_t)3 * B_DIM * 256 + base + q * 4);
            float4 bb = *(const float4*)(bd + l16 * 16 + q * 4);
            d[q * 4 + 0] = t0.x + t1.x + t2.x + t3.x + bb.x;
            d[q * 4 + 1] = t0.y + t1.y + t2.y + t3.y + bb.y;
            d[q * 4 + 2] = t0.z + t1.z + t2.z + t3.z + bb.z;
            d[q * 4 + 3] = t0.w + t1.w + t2.w + t3.w + bb.w;
        }
        float mx = d[0];
        #pragma unroll
        for (int j = 1; j < 16; j++) mx = fmaxf(mx, d[j]);
        float s = 0.f;
        #pragma unroll
        for (int j = 0; j < 16; j++) { d[j] = expf(d[j] - mx); s += d[j]; }
        float inv = 1.f / s;
        #pragma unroll
        for (int j = 0; j < 16; j++) d[j] *= inv;
    }

    #pragma unroll
    for (int m = 1; m < 16; m <<= 1) {
        float u[16];
        #pragma unroll
        for (int i = 0; i < 16; i++)
            u[i] = __shfl_xor_sync(0xffffffffu, d[i ^ m], m);
        #pragma unroll
        for (int i = 0; i < 16; i++)
            if ((i & m) != (l16 & m)) d[i] = u[i];
    }

    float diag = 0.f;
    #pragma unroll
    for (int i = 0; i < 16; i++)
        if (i == l16) diag = d[i];

    float row[17];
    #pragma unroll
    for (int n = 0; n < 16; n++)
        row[n] = (n == l16) ? 1.f : -ome * d[n];
    row[16] = 1.f;

    #pragma unroll
    for (int p = 0; p < 16; p++) {
        float pivot = __shfl_sync(0xffffffffu, row[p], p, 16);
        float inv = 1.f / pivot;
        float f = row[p];
        #pragma unroll
        for (int c = p; c < 17; c++) {
            float pc = __shfl_sync(0xffffffffu, row[c], p, 16) * inv;
            if (l16 == p)      row[c] = pc;
            else if (l16 > p)  row[c] -= f * pc;
        }
    }

    float s = row[16];
    float z = 0.f;
    #pragma unroll
    for (int r = 15; r >= 0; r--) {
        float zr = __shfl_sync(0xffffffffu, s, r, 16);
        if (l16 == r) z = zr;
        if (l16 < r)  s -= row[r] * zr;
    }

    float zs = z;
    #pragma unroll
    for (int m = 8; m >= 1; m >>= 1)
        zs += __shfl_xor_sync(0xffffffffu, zs, m);
    float z16 = 1.f + EPSV * zs;
    float add = z16 * (1.f / 16.f) - (1.f / 16.f);
    g_power[(size_t)b * 16 + l16] = z * ome * diag + add;
}

// ============================================================================
// main_gemm: fp16 single-pass, K-chunk 64, 512 threads, warp tile 32x64.
// Buffer (48KB): A[16K] B[32K], 128B rows (sw128). 257 stages.
// ============================================================================
#define MBUFSTRIDE 49152
#define MSMEM_TOTAL (2 * MBUFSTRIDE)
#define NSTG 257

__device__ __forceinline__ void cp_b_main(uint32_t buf, int bn, int t, int tid)
{
    const int row = tid >> 1;          // 0..255 (full 256-row B tile)
    const int q0 = (tid & 1) * 4;      // 0 or 4: 4 granules (64B) per thread
    const char* sh;
    if (t < 256) {
        size_t off = ((size_t)(bn + row) * KTOT +
                      (size_t)(t & 15) * 1024 + (size_t)(t >> 4) * 64) * 2;
        sh = (const char*)g_wf16 + off;
    } else {
        sh = (const char*)g_byf16 + (size_t)(bn + row) * 128;
    }
    uint32_t bb = buf + 16384;
    #pragma unroll
    for (int i = 0; i < 4; i++)
        CP_ASYNC16(sw128(bb, row, q0 + i), sh + (q0 + i) * 16);
}

// A gen: a = fp16(p*x), 16 k values per thread. Thread: row tid>>2, sub tid&3.
__device__ __forceinline__ void gen_a_main(uint32_t buf, int bm, int t, int tid,
                                           const float* xv)
{
    const int ar = tid >> 2;
    const int sub = tid & 3;
    float v[16];
    float p;
    if (t < 256) {
        const int n = t & 15;
        p = g_power[(size_t)(bm + ar) * 16 + n];
        #pragma unroll
        for (int i = 0; i < 16; i++) v[i] = xv[i];
    } else {
        p = 1.f;
        if (sub == 0) {
            const float* pp = &g_power[(size_t)(bm + ar) * 16];
            #pragma unroll
            for (int q = 0; q < 4; q++) {
                float4 a = *(const float4*)(pp + q * 4);
                v[q * 4 + 0] = a.x; v[q * 4 + 1] = a.y;
                v[q * 4 + 2] = a.z; v[q * 4 + 3] = a.w;
            }
        } else {
            #pragma unroll
            for (int i = 0; i < 16; i++) v[i] = 0.f;
        }
    }
    uint32_t hv[8];
    #pragma unroll
    for (int i = 0; i < 8; i++)
        hv[i] = pack_f16f(v[i * 2] * p, v[i * 2 + 1] * p);
    STS128(sw128(buf, ar, sub * 2),     hv[0], hv[1], hv[2], hv[3]);
    STS128(sw128(buf, ar, sub * 2 + 1), hv[4], hv[5], hv[6], hv[7]);
}

// one k16 math step (kh 0..3), warp tile 32x64, single fp16 pass
__device__ __forceinline__ void math_f16(uint32_t cb, int kh, int wm, int wn,
                                         int j, int rr, float acc[2][8][4])
{
    uint32_t af[2][4];
    #pragma unroll
    for (int t = 0; t < 2; t++) {
        int row = wm + t * 16 + ((j & 1) << 3) + rr;
        int q = kh * 2 + (j >> 1);
        LDSM4(af[t], sw128(cb, row, q));
    }
    #pragma unroll
    for (int uh = 0; uh < 2; uh++) {
        uint32_t bf[4][2];
        #pragma unroll
        for (int up = 0; up < 2; up++) {
            int u0 = uh * 4 + up * 2;
            int nrow = wn + u0 * 8 + ((j >> 1) << 3) + rr;
            int q = kh * 2 + (j & 1);
            uint32_t t4[4];
            LDSM4(t4, sw128(cb + 16384, nrow, q));
            bf[up * 2][0] = t4[0]; bf[up * 2][1] = t4[1];
            bf[up * 2 + 1][0] = t4[2]; bf[up * 2 + 1][1] = t4[3];
        }
        #pragma unroll
        for (int t = 0; t < 2; t++)
            #pragma unroll
            for (int uu = 0; uu < 4; uu++)
                MMA_F16(acc[t][uh * 4 + uu], af[t], bf[uu]);
    }
}

__global__ __launch_bounds__(512, 1) void main_gemm(
    const float* __restrict__ x, float* __restrict__ out)
{
    extern __shared__ char smem[];
    const uint32_t sb = smem_to_u32(smem);
    const int tid = threadIdx.x;
    const int lane = tid & 31, w = tid >> 5;
    const int bm = blockIdx.y * 128;
    const int bn = blockIdx.x * 256;
    const int wm = (w & 3) * 32, wn = (w >> 2) * 64;

    float acc[2][8][4];
    #pragma unroll
    for (int t = 0; t < 2; t++)
        #pragma unroll
        for (int u = 0; u < 8; u++)
            #pragma unroll
            for (int c = 0; c < 4; c++) acc[t][u][c] = 0.f;

    const int ar = tid >> 2;
    const float* xbase = x + (size_t)(bm + ar) * D_IN + (tid & 3) * 16;
    float xv[16];
    #pragma unroll
    for (int q = 0; q < 4; q++) {
        float4 a = *(const float4*)(xbase + q * 4);
        xv[q * 4 + 0] = a.x; xv[q * 4 + 1] = a.y;
        xv[q * 4 + 2] = a.z; xv[q * 4 + 3] = a.w;
    }

    cp_b_main(sb, bn, 0, tid);
    CP_COMMIT();
    gen_a_main(sb, bm, 0, tid, xv);
    CP_WAIT0();
    __syncthreads();

    const int j = lane >> 3, rr = lane & 7;

    for (int s = 0; s < NSTG; s++) {
        const uint32_t cb = sb + (uint32_t)(s & 1) * MBUFSTRIDE;
        const uint32_t nb = sb + (uint32_t)((s + 1) & 1) * MBUFSTRIDE;
        const bool has_next = (s + 1 < NSTG);

        if (has_next) {
            cp_b_main(nb, bn, s + 1, tid);
            CP_COMMIT();
        }
        math_f16(cb, 0, wm, wn, j, rr, acc);
        math_f16(cb, 1, wm, wn, j, rr, acc);
        if (has_next) {
            const int t = s + 1;
            if ((t & 15) == 0 && t < 256) {   // new o-chunk: refresh x cache
                const float* xp = xbase + (t >> 4) * 64;
                #pragma unroll
                for (int q = 0; q < 4; q++) {
                    float4 a = *(const float4*)(xp + q * 4);
                    xv[q * 4 + 0] = a.x; xv[q * 4 + 1] = a.y;
                    xv[q * 4 + 2] = a.z; xv[q * 4 + 3] = a.w;
                }
            }
            gen_a_main(nb, bm, t, tid, xv);
        }
        math_f16(cb, 2, wm, wn, j, rr, acc);
        math_f16(cb, 3, wm, wn, j, rr, acc);
        if (has_next) CP_WAIT0();
        __syncthreads();
    }

    #pragma unroll
    for (int t = 0; t < 2; t++) {
        int row0 = bm + wm + t * 16 + (lane >> 2);
        #pragma unroll
        for (int u = 0; u < 8; u++) {
            int col = bn + wn + u * 8 + (lane & 3) * 2;
            *(float2*)&out[(size_t)row0 * D_OUT + col] =
                make_float2(acc[t][u][0], acc[t][u][1]);
            *(float2*)&out[(size_t)(row0 + 8) * D_OUT + col] =
                make_float2(acc[t][u][2], acc[t][u][3]);
        }
    }
}

// ============================================================================
extern "C" void kernel_launch(void* const* d_in, const int* in_sizes, int n_in,
                              void* d_out, int out_size)
{
    const float* x  = (const float*)d_in[0];
    const float* Wy = (const float*)d_in[1];
    const float* by = (const float*)d_in[2];
    const float* Wd = (const float*)d_in[3];
    const float* bd = (const float*)d_in[4];
    float* out = (float*)d_out;

    cudaFuncSetAttribute(main_gemm, cudaFuncAttributeMaxDynamicSharedMemorySize,
                         MSMEM_TOTAL);
    cudaFuncSetAttribute(logits_mma, cudaFuncAttributeMaxDynamicSharedMemorySize,
                         LSMEM_TOTAL);

    transpose_f16<<<dim3(KTOT / 64, D_OUT / 64), 256>>>(Wy);
    by_prep<<<D_OUT / 256, 256>>>(by);
    wd_prep<<<256, 256>>>(Wd);
    logits_mma<<<dim3(LSPLIT, B_DIM / 128), 256, LSMEM_TOTAL>>>(x);
    power_kernel<<<B_DIM / 16, 256>>>(bd);
    main_gemm<<<dim3(D_OUT / 256, B_DIM / 128), 512, MSMEM_TOTAL>>>(x, out);
}